// round 6
// baseline (speedup 1.0000x reference)
#include <cuda_runtime.h>
#include <cuda_bf16.h>
#include <cstdint>

#define GAMMA 0.001f
#define NIMG 4096
#define MSUP 8192
#define KDIM 784
#define KPAD 800
#define NCLS 4

#define TI 256
#define TJ 128
#define KC 32
#define STA 40                 // padded smem row stride (elems): 80B, conflict-free
#define NSTAGE (KPAD / KC)     // 25
#define NJT (MSUP / TJ)        // 64
#define NIT (NIMG / TI)        // 16

// ---- gemm dynamic smem layout (bytes) ----
#define OFF_A 0                          // 4 x TI*STA*2 = 81920
#define OFF_B 81920                      // 4 x TJ*STA*2 = 40960
#define OFF_S2 122880                    // 512
#define OFF_F2 123392                    // 1024
#define OFF_AL 124416                    // 2048
#define GEMM_SMEM 126464

// ---- device scratch (no allocs allowed) ----
__device__ __nv_bfloat16 g_featsB[NIMG * KPAD];
__device__ __nv_bfloat16 g_supB[MSUP * KPAD];
__device__ float g_s2[MSUP];
__device__ float g_f2[NIMG];
__device__ float g_part[NJT * NIMG * NCLS];

// ---------------------------------------------------------------------------
__device__ __forceinline__ uint32_t smem_u32(const void* p) {
    uint32_t a;
    asm("{ .reg .u64 t; cvta.to.shared.u64 t, %1; cvt.u32.u64 %0, t; }" : "=r"(a) : "l"(p));
    return a;
}
__device__ __forceinline__ void cp16(uint32_t smem, const void* gmem) {
    asm volatile("cp.async.cg.shared.global [%0], [%1], 16;" :: "r"(smem), "l"(gmem));
}
__device__ __forceinline__ void ldm_x4(uint32_t* r, uint32_t addr) {
    asm volatile("ldmatrix.sync.aligned.m8n8.x4.shared.b16 {%0,%1,%2,%3}, [%4];"
                 : "=r"(r[0]), "=r"(r[1]), "=r"(r[2]), "=r"(r[3]) : "r"(addr));
}
__device__ __forceinline__ void mma_bf16(float* d, const uint32_t* a, uint32_t b0, uint32_t b1) {
    asm volatile(
        "mma.sync.aligned.m16n8k16.row.col.f32.bf16.bf16.f32 "
        "{%0,%1,%2,%3}, {%4,%5,%6,%7}, {%8,%9}, {%0,%1,%2,%3};"
        : "+f"(d[0]), "+f"(d[1]), "+f"(d[2]), "+f"(d[3])
        : "r"(a[0]), "r"(a[1]), "r"(a[2]), "r"(a[3]), "r"(b0), "r"(b1));
}

// ---------------------------------------------------------------------------
// Conv: 1 image per 256-thread block, 224 active compute lanes.
// conv1: thread pair splits the 14 pooled rows (7 each, own sliding window).
// conv2: thread pair splits the 8 input channels (4 each) + shfl_xor combine.
// Fuses bf16 feat store + f2 (sum of squares of rounded feats).
// ---------------------------------------------------------------------------
__global__ void __launch_bounds__(256) conv_kernel(
    const float* __restrict__ x,
    const float* __restrict__ w1, const float* __restrict__ b1,
    const float* __restrict__ w2, const float* __restrict__ b2)
{
    __shared__ float sx[900];             // 30x30 padded (+1)
    __shared__ float sp1[2048];           // 8 x 16x16 padded (+1)
    __shared__ float sw1[72], sb1[8], sw2[1152], sb2[16];
    __shared__ float sred[8];

    const int tid = threadIdx.x;
    const int n = blockIdx.x;

    for (int i = tid; i < 900; i += 256) sx[i] = 0.f;
    for (int i = tid; i < 2048; i += 256) sp1[i] = 0.f;
    for (int i = tid; i < 72; i += 256) sw1[i] = w1[i];
    if (tid < 8) sb1[tid] = b1[tid];
    for (int i = tid; i < 1152; i += 256) sw2[i] = w2[i];
    if (tid < 16) sb2[tid] = b2[tid];
    __syncthreads();

    const float* xn = x + (size_t)n * 784;
    for (int i = tid; i < 784; i += 256) {
        int yy = i / 28, xx = i % 28;
        sx[(yy + 1) * 30 + xx + 1] = xn[i];
    }
    __syncthreads();

    // ---- conv1 + relu + pool: pair = (c in 0..7, px in 0..13), half = py range ----
    if (tid < 224) {
        const int idx = tid >> 1, h = tid & 1;
        const int c = idx & 7, px = idx >> 3;
        const int py0 = h * 7;
        float w[9];
        #pragma unroll
        for (int k = 0; k < 9; k++) w[k] = sw1[c * 9 + k];
        const float bb = sb1[c];
        float W[4][4];
        #pragma unroll
        for (int pp = 0; pp < 7; pp++) {
            const int py = py0 + pp;
            if (pp == 0) {
                #pragma unroll
                for (int r = 0; r < 4; r++)
                    #pragma unroll
                    for (int cc = 0; cc < 4; cc++)
                        W[r][cc] = sx[(2 * py + r) * 30 + 2 * px + cc];
            } else {
                #pragma unroll
                for (int cc = 0; cc < 4; cc++) { W[0][cc] = W[2][cc]; W[1][cc] = W[3][cc]; }
                #pragma unroll
                for (int r = 2; r < 4; r++)
                    #pragma unroll
                    for (int cc = 0; cc < 4; cc++)
                        W[r][cc] = sx[(2 * py + r) * 30 + 2 * px + cc];
            }
            float m = 0.f;
            #pragma unroll
            for (int sy = 0; sy < 2; sy++)
                #pragma unroll
                for (int sxx = 0; sxx < 2; sxx++) {
                    float acc = bb;
                    #pragma unroll
                    for (int dy = 0; dy < 3; dy++)
                        #pragma unroll
                        for (int dx = 0; dx < 3; dx++)
                            acc += w[dy * 3 + dx] * W[sy + dy][sxx + dx];
                    m = fmaxf(m, fmaxf(acc, 0.f));
                }
            sp1[c * 256 + (py + 1) * 16 + px + 1] = m;
        }
    }
    __syncthreads();

    // ---- conv2 + relu + pool: pair = (c in 0..15, px in 0..6), half = ic range ----
    float sq = 0.f;
    if (tid < 224) {
        const int idx = tid >> 1, h = tid & 1;
        const int px = idx % 7, c = idx / 7;
        float acc[7][4];
        const float bb = (h == 0) ? sb2[c] : 0.f;
        #pragma unroll
        for (int py = 0; py < 7; py++)
            #pragma unroll
            for (int q = 0; q < 4; q++) acc[py][q] = bb;

        #pragma unroll
        for (int ict = 0; ict < 4; ict++) {
            const int ic = h * 4 + ict;
            float w[9];
            #pragma unroll
            for (int k = 0; k < 9; k++) w[k] = sw2[c * 72 + ic * 9 + k];
            const float* sp = sp1 + ic * 256;
            float W[4][4];
            #pragma unroll
            for (int py = 0; py < 7; py++) {
                if (py == 0) {
                    #pragma unroll
                    for (int r = 0; r < 4; r++)
                        #pragma unroll
                        for (int cc = 0; cc < 4; cc++)
                            W[r][cc] = sp[r * 16 + 2 * px + cc];
                } else {
                    #pragma unroll
                    for (int cc = 0; cc < 4; cc++) { W[0][cc] = W[2][cc]; W[1][cc] = W[3][cc]; }
                    #pragma unroll
                    for (int r = 2; r < 4; r++)
                        #pragma unroll
                        for (int cc = 0; cc < 4; cc++)
                            W[r][cc] = sp[(2 * py + r) * 16 + 2 * px + cc];
                }
                #pragma unroll
                for (int sy = 0; sy < 2; sy++)
                    #pragma unroll
                    for (int sxx = 0; sxx < 2; sxx++) {
                        float a2 = 0.f;
                        #pragma unroll
                        for (int dy = 0; dy < 3; dy++)
                            #pragma unroll
                            for (int dx = 0; dx < 3; dx++)
                                a2 += w[dy * 3 + dx] * W[sy + dy][sxx + dx];
                        acc[py][sy * 2 + sxx] += a2;
                    }
            }
        }
        // combine the two ic-halves (adjacent lanes)
        #pragma unroll
        for (int py = 0; py < 7; py++)
            #pragma unroll
            for (int q = 0; q < 4; q++)
                acc[py][q] += __shfl_xor_sync(0xffffffffu, acc[py][q], 1);

        if (h == 0) {
            __nv_bfloat16* fdst = g_featsB + (size_t)n * KPAD + c * 49 + px;
            #pragma unroll
            for (int py = 0; py < 7; py++) {
                float m = 0.f;
                #pragma unroll
                for (int q = 0; q < 4; q++) m = fmaxf(m, fmaxf(acc[py][q], 0.f));
                __nv_bfloat16 bv = __float2bfloat16(m);
                fdst[py * 7] = bv;
                float fv = __bfloat162float(bv);
                sq += fv * fv;
            }
        }
    }
    if (tid < KPAD - KDIM)
        g_featsB[(size_t)n * KPAD + KDIM + tid] = __float2bfloat16(0.f);

    // f2 block reduction (8 warps)
    #pragma unroll
    for (int off = 16; off; off >>= 1) sq += __shfl_xor_sync(0xffffffffu, sq, off);
    if ((tid & 31) == 0) sred[tid >> 5] = sq;
    __syncthreads();
    if (tid == 0) {
        float s = 0.f;
        #pragma unroll
        for (int wv = 0; wv < 8; wv++) s += sred[wv];
        g_f2[n] = s;
    }
}

// ---------------------------------------------------------------------------
// support -> g_supB (bf16) + g_s2 (fp32 from rounded). One warp per row.
// ---------------------------------------------------------------------------
__global__ void __launch_bounds__(256) prep_support(const float* __restrict__ support)
{
    int row = blockIdx.x * 8 + (threadIdx.x >> 5);
    int lane = threadIdx.x & 31;
    if (row >= MSUP) return;
    const float* src = support + (size_t)row * KDIM;
    __nv_bfloat16* dst = g_supB + (size_t)row * KPAD;
    float s = 0.f;
    for (int k = lane; k < KDIM; k += 32) {
        __nv_bfloat16 b = __float2bfloat16(src[k]);
        dst[k] = b;
        float v = __bfloat162float(b);
        s += v * v;
    }
    if (lane < KPAD - KDIM) dst[KDIM + lane] = __float2bfloat16(0.f);
    #pragma unroll
    for (int off = 16; off; off >>= 1) s += __shfl_xor_sync(0xffffffffu, s, off);
    if (lane == 0) g_s2[row] = s;
}

// ---------------------------------------------------------------------------
// bf16 mma.sync fused GEMM: 256x128 CTA tile, 512 threads, 16 warps,
// 4-stage cp.async ring with ONE __syncthreads per stage.
// ---------------------------------------------------------------------------
__global__ void __launch_bounds__(512, 1) gemm_mma(const float* __restrict__ alpha)
{
    extern __shared__ char dsm[];
    float* s2s = (float*)(dsm + OFF_S2);
    float* f2s = (float*)(dsm + OFF_F2);
    float4* als = (float4*)(dsm + OFF_AL);
    float* red = (float*)(dsm + OFF_A);   // reused after mainloop (16KB)

    const int tid = threadIdx.x;
    const int lane = tid & 31, wid = tid >> 5;
    const int wi = wid >> 2;        // 0..3 : 64-row slice
    const int wj = wid & 3;         // 0..3 : 32-col slice
    const int ibase = blockIdx.x * TI;
    const int jbase = blockIdx.y * TJ;

    if (tid < TI) f2s[tid] = g_f2[ibase + tid];
    if (tid < TJ) {
        s2s[tid] = g_s2[jbase + tid];
        als[tid] = ((const float4*)alpha)[jbase + tid];
    }

    uint32_t aBase[4], bBase[4];
    #pragma unroll
    for (int b = 0; b < 4; b++) {
        aBase[b] = smem_u32(dsm + OFF_A + b * TI * STA * 2);
        bBase[b] = smem_u32(dsm + OFF_B + b * TJ * STA * 2);
    }
    const __nv_bfloat16* gA = g_featsB + (size_t)ibase * KPAD;
    const __nv_bfloat16* gB = g_supB + (size_t)jbase * KPAD;

    float acc[4][4][4];
    #pragma unroll
    for (int mi = 0; mi < 4; mi++)
        #pragma unroll
        for (int nj = 0; nj < 4; nj++)
            #pragma unroll
            for (int e = 0; e < 4; e++) acc[mi][nj][e] = 0.f;

    auto prefetch = [&](int s, int b) {
        #pragma unroll
        for (int tcnt = 0; tcnt < 2; tcnt++) {        // A: 256 rows x 4 chunks
            int id = tid + tcnt * 512;
            int r = id >> 2, c = id & 3;
            cp16(aBase[b] + (r * STA + c * 8) * 2, gA + (size_t)r * KPAD + s * KC + c * 8);
        }
        {                                              // B: 128 rows x 4 chunks
            int r = tid >> 2, c = tid & 3;
            cp16(bBase[b] + (r * STA + c * 8) * 2, gB + (size_t)r * KPAD + s * KC + c * 8);
        }
        asm volatile("cp.async.commit_group;" ::: "memory");
    };

    prefetch(0, 0);
    prefetch(1, 1);

    const int a_row = (lane & 15);
    const int a_koff = (lane >> 4) * 8;
    const int b_nrow = ((lane >> 4) & 1) * 8 + (lane & 7);
    const int b_koff = ((lane >> 3) & 1) * 8;

    for (int s = 0; s < NSTAGE; s++) {
        if (s + 1 < NSTAGE) {
            asm volatile("cp.async.wait_group 1;" ::: "memory");
        } else {
            asm volatile("cp.async.wait_group 0;" ::: "memory");
        }
        __syncthreads();
        if (s + 2 < NSTAGE) prefetch(s + 2, (s + 2) & 3);

        const int b = s & 3;
        #pragma unroll
        for (int ks = 0; ks < 2; ks++) {
            uint32_t afr[4][4];
            #pragma unroll
            for (int mi = 0; mi < 4; mi++) {
                uint32_t addr = aBase[b] +
                    ((wi * 64 + mi * 16 + a_row) * STA + ks * 16 + a_koff) * 2;
                ldm_x4(afr[mi], addr);
            }
            uint32_t bfr[2][4];
            #pragma unroll
            for (int njp = 0; njp < 2; njp++) {
                uint32_t addr = bBase[b] +
                    ((wj * 32 + njp * 16 + b_nrow) * STA + ks * 16 + b_koff) * 2;
                ldm_x4(bfr[njp], addr);
            }
            #pragma unroll
            for (int mi = 0; mi < 4; mi++)
                #pragma unroll
                for (int nj = 0; nj < 4; nj++)
                    mma_bf16(acc[mi][nj], afr[mi],
                             bfr[nj >> 1][(nj & 1) * 2 + 0],
                             bfr[nj >> 1][(nj & 1) * 2 + 1]);
        }
    }

    // ---------------- epilogue: RBF + alpha, fused ----------------
    const int r0 = lane >> 2;
    const int c0 = (lane & 3) * 2;
    float po[8][4];
    #pragma unroll
    for (int i = 0; i < 8; i++)
        #pragma unroll
        for (int c = 0; c < 4; c++) po[i][c] = 0.f;

    #pragma unroll
    for (int mi = 0; mi < 4; mi++)
        #pragma unroll
        for (int nj = 0; nj < 4; nj++)
            #pragma unroll
            for (int e = 0; e < 4; e++) {
                int h = e >> 1;
                int rowl = wi * 64 + mi * 16 + r0 + h * 8;
                int coll = wj * 32 + nj * 8 + c0 + (e & 1);
                float d2 = f2s[rowl] + s2s[coll] - 2.0f * acc[mi][nj][e];
                float kv = __expf(-GAMMA * d2);
                float4 al = als[coll];
                po[mi * 2 + h][0] += kv * al.x;
                po[mi * 2 + h][1] += kv * al.y;
                po[mi * 2 + h][2] += kv * al.z;
                po[mi * 2 + h][3] += kv * al.w;
            }

    #pragma unroll
    for (int off = 1; off <= 2; off <<= 1)
        #pragma unroll
        for (int i = 0; i < 8; i++)
            #pragma unroll
            for (int c = 0; c < 4; c++)
                po[i][c] += __shfl_xor_sync(0xffffffffu, po[i][c], off);

    __syncthreads();   // last stage's ldmatrix reads (buf 0) before red overwrite

    if ((lane & 3) == 0) {
        #pragma unroll
        for (int i = 0; i < 8; i++) {
            int mi = i >> 1, h = i & 1;
            int rowl = wi * 64 + mi * 16 + r0 + h * 8;
            #pragma unroll
            for (int c = 0; c < 4; c++)
                red[(wj * TI + rowl) * 4 + c] = po[i][c];
        }
    }
    __syncthreads();

    for (int id = tid; id < TI * NCLS; id += 512) {
        int rowl = id >> 2, c = id & 3;
        float sum = red[(0 * TI + rowl) * 4 + c] + red[(1 * TI + rowl) * 4 + c]
                  + red[(2 * TI + rowl) * 4 + c] + red[(3 * TI + rowl) * 4 + c];
        g_part[(size_t)blockIdx.y * NIMG * NCLS + (size_t)(ibase + rowl) * NCLS + c] = sum;
    }
}

__global__ void combine_kernel(float* __restrict__ out)
{
    int i = blockIdx.x * blockDim.x + threadIdx.x;
    if (i >= NIMG * NCLS) return;
    float s = 0.f;
    #pragma unroll 8
    for (int p = 0; p < NJT; p++) s += g_part[(size_t)p * NIMG * NCLS + i];
    out[i] = s;
}

// ---------------------------------------------------------------------------
extern "C" void kernel_launch(void* const* d_in, const int* in_sizes, int n_in,
                              void* d_out, int out_size)
{
    const float* x       = (const float*)d_in[0];
    const float* w1      = (const float*)d_in[1];
    const float* b1      = (const float*)d_in[2];
    const float* w2      = (const float*)d_in[3];
    const float* b2      = (const float*)d_in[4];
    const float* support = (const float*)d_in[5];
    const float* alpha   = (const float*)d_in[6];
    float* out = (float*)d_out;

    static bool attr_set = false;
    if (!attr_set) {
        cudaFuncSetAttribute(gemm_mma, cudaFuncAttributeMaxDynamicSharedMemorySize, GEMM_SMEM);
        attr_set = true;
    }

    conv_kernel<<<NIMG, 256>>>(x, w1, b1, w2, b2);
    prep_support<<<MSUP / 8, 256>>>(support);
    gemm_mma<<<dim3(NIT, NJT), 512, GEMM_SMEM>>>(alpha);
    combine_kernel<<<(NIMG * NCLS + 255) / 256, 256>>>(out);
}

// round 7
// speedup vs baseline: 1.1347x; 1.1347x over previous
#include <cuda_runtime.h>
#include <cuda_bf16.h>
#include <cstdint>

#define GAMMA 0.001f
#define NIMG 4096
#define MSUP 8192
#define KDIM 784
#define KPAD 800
#define NCLS 4

#define TI 128
#define TJ 128
#define KC 32
#define STA 40                 // padded smem row stride (elems): 80B, conflict-free
#define NSTAGE (KPAD / KC)     // 25
#define NJT (MSUP / TJ)        // 64
#define NIT (NIMG / TI)        // 32

// ---- gemm dynamic smem layout (bytes) ----
#define OFF_A 0                          // 3 x TI*STA bf16 = 30720
#define OFF_B 30720                      // 3 x TJ*STA bf16 = 30720
#define OFF_S2 61440                     // 512
#define OFF_F2 61952                     // 512
#define OFF_AL 62464                     // 2048
#define GEMM_SMEM 64512

// ---- device scratch (no allocs allowed) ----
__device__ __nv_bfloat16 g_featsB[NIMG * KPAD];
__device__ __nv_bfloat16 g_supB[MSUP * KPAD];
__device__ float g_s2[MSUP];
__device__ float g_f2[NIMG];
__device__ float g_part[NJT * NIMG * NCLS];

// ---------------------------------------------------------------------------
__device__ __forceinline__ uint32_t smem_u32(const void* p) {
    uint32_t a;
    asm("{ .reg .u64 t; cvta.to.shared.u64 t, %1; cvt.u32.u64 %0, t; }" : "=r"(a) : "l"(p));
    return a;
}
__device__ __forceinline__ void cp16(uint32_t smem, const void* gmem) {
    asm volatile("cp.async.cg.shared.global [%0], [%1], 16;" :: "r"(smem), "l"(gmem));
}
__device__ __forceinline__ void ldm_x4(uint32_t* r, uint32_t addr) {
    asm volatile("ldmatrix.sync.aligned.m8n8.x4.shared.b16 {%0,%1,%2,%3}, [%4];"
                 : "=r"(r[0]), "=r"(r[1]), "=r"(r[2]), "=r"(r[3]) : "r"(addr));
}
__device__ __forceinline__ void mma_bf16(float* d, const uint32_t* a, uint32_t b0, uint32_t b1) {
    asm volatile(
        "mma.sync.aligned.m16n8k16.row.col.f32.bf16.bf16.f32 "
        "{%0,%1,%2,%3}, {%4,%5,%6,%7}, {%8,%9}, {%0,%1,%2,%3};"
        : "+f"(d[0]), "+f"(d[1]), "+f"(d[2]), "+f"(d[3])
        : "r"(a[0]), "r"(a[1]), "r"(a[2]), "r"(a[3]), "r"(b0), "r"(b1));
}

// ---------------------------------------------------------------------------
// Conv (R5 version): 2 images per 256-thread block; register sliding-window.
// Fuses bf16 feat store + f2 (sum of squares of rounded feats).
// ---------------------------------------------------------------------------
__global__ void __launch_bounds__(256) conv_kernel(
    const float* __restrict__ x,
    const float* __restrict__ w1, const float* __restrict__ b1,
    const float* __restrict__ w2, const float* __restrict__ b2)
{
    __shared__ float sx[2][900];          // 30x30 padded (+1)
    __shared__ float sp1[2][2048];        // 8 x 16x16 padded (+1)
    __shared__ float sw1[72], sb1[8], sw2[1152], sb2[16];
    __shared__ float sred[2][4];

    const int tid = threadIdx.x;
    const int img = tid >> 7;
    const int t = tid & 127;
    const int n = blockIdx.x * 2 + img;

    for (int i = tid; i < 1800; i += 256) ((float*)sx)[i] = 0.f;
    for (int i = tid; i < 4096; i += 256) ((float*)sp1)[i] = 0.f;
    for (int i = tid; i < 72; i += 256) sw1[i] = w1[i];
    if (tid < 8) sb1[tid] = b1[tid];
    for (int i = tid; i < 1152; i += 256) sw2[i] = w2[i];
    if (tid < 16) sb2[tid] = b2[tid];
    __syncthreads();

    const float* xn = x + (size_t)n * 784;
    for (int i = t; i < 784; i += 128) {
        int yy = i / 28, xx = i % 28;
        sx[img][(yy + 1) * 30 + xx + 1] = xn[i];
    }
    __syncthreads();

    // ---- conv1 + relu + pool: thread = (c in 0..7, px in 0..13) ----
    if (t < 112) {
        const int c = t & 7, px = t >> 3;
        float w[9];
        #pragma unroll
        for (int k = 0; k < 9; k++) w[k] = sw1[c * 9 + k];
        const float bb = sb1[c];
        const float* sxi = sx[img];
        float W[4][4];
        #pragma unroll
        for (int py = 0; py < 14; py++) {
            if (py == 0) {
                #pragma unroll
                for (int r = 0; r < 4; r++)
                    #pragma unroll
                    for (int cc = 0; cc < 4; cc++)
                        W[r][cc] = sxi[r * 30 + 2 * px + cc];
            } else {
                #pragma unroll
                for (int cc = 0; cc < 4; cc++) { W[0][cc] = W[2][cc]; W[1][cc] = W[3][cc]; }
                #pragma unroll
                for (int r = 2; r < 4; r++)
                    #pragma unroll
                    for (int cc = 0; cc < 4; cc++)
                        W[r][cc] = sxi[(2 * py + r) * 30 + 2 * px + cc];
            }
            float m = 0.f;
            #pragma unroll
            for (int sy = 0; sy < 2; sy++)
                #pragma unroll
                for (int sxx = 0; sxx < 2; sxx++) {
                    float acc = bb;
                    #pragma unroll
                    for (int dy = 0; dy < 3; dy++)
                        #pragma unroll
                        for (int dx = 0; dx < 3; dx++)
                            acc += w[dy * 3 + dx] * W[sy + dy][sxx + dx];
                    m = fmaxf(m, fmaxf(acc, 0.f));
                }
            sp1[img][c * 256 + (py + 1) * 16 + px + 1] = m;
        }
    }
    __syncthreads();

    // ---- conv2 + relu + pool: thread = (c in 0..15, px in 0..6) ----
    float sq = 0.f;
    if (t < 112) {
        const int px = t % 7, c = t / 7;
        float acc[7][4];
        const float bb = sb2[c];
        #pragma unroll
        for (int py = 0; py < 7; py++)
            #pragma unroll
            for (int q = 0; q < 4; q++) acc[py][q] = bb;

        #pragma unroll
        for (int ic = 0; ic < 8; ic++) {
            float w[9];
            #pragma unroll
            for (int k = 0; k < 9; k++) w[k] = sw2[c * 72 + ic * 9 + k];
            const float* sp = sp1[img] + ic * 256;
            float W[4][4];
            #pragma unroll
            for (int py = 0; py < 7; py++) {
                if (py == 0) {
                    #pragma unroll
                    for (int r = 0; r < 4; r++)
                        #pragma unroll
                        for (int cc = 0; cc < 4; cc++)
                            W[r][cc] = sp[r * 16 + 2 * px + cc];
                } else {
                    #pragma unroll
                    for (int cc = 0; cc < 4; cc++) { W[0][cc] = W[2][cc]; W[1][cc] = W[3][cc]; }
                    #pragma unroll
                    for (int r = 2; r < 4; r++)
                        #pragma unroll
                        for (int cc = 0; cc < 4; cc++)
                            W[r][cc] = sp[(2 * py + r) * 16 + 2 * px + cc];
                }
                #pragma unroll
                for (int sy = 0; sy < 2; sy++)
                    #pragma unroll
                    for (int sxx = 0; sxx < 2; sxx++) {
                        float a2 = 0.f;
                        #pragma unroll
                        for (int dy = 0; dy < 3; dy++)
                            #pragma unroll
                            for (int dx = 0; dx < 3; dx++)
                                a2 += w[dy * 3 + dx] * W[sy + dy][sxx + dx];
                        acc[py][sy * 2 + sxx] += a2;
                    }
            }
        }
        __nv_bfloat16* fdst = g_featsB + (size_t)n * KPAD + c * 49 + px;
        #pragma unroll
        for (int py = 0; py < 7; py++) {
            float m = 0.f;
            #pragma unroll
            for (int q = 0; q < 4; q++) m = fmaxf(m, fmaxf(acc[py][q], 0.f));
            __nv_bfloat16 bv = __float2bfloat16(m);
            fdst[py * 7] = bv;
            float fv = __bfloat162float(bv);
            sq += fv * fv;
        }
    }
    if (t < KPAD - KDIM)
        g_featsB[(size_t)n * KPAD + KDIM + t] = __float2bfloat16(0.f);

    // f2 block reduction (per image: 4 warps)
    #pragma unroll
    for (int off = 16; off; off >>= 1) sq += __shfl_xor_sync(0xffffffffu, sq, off);
    if ((t & 31) == 0) sred[img][(t >> 5) & 3] = sq;
    __syncthreads();
    if (t == 0) g_f2[n] = sred[img][0] + sred[img][1] + sred[img][2] + sred[img][3];
}

// ---------------------------------------------------------------------------
// support -> g_supB (bf16) + g_s2 (fp32 from rounded). One warp per row.
// ---------------------------------------------------------------------------
__global__ void __launch_bounds__(256) prep_support(const float* __restrict__ support)
{
    int row = blockIdx.x * 8 + (threadIdx.x >> 5);
    int lane = threadIdx.x & 31;
    if (row >= MSUP) return;
    const float* src = support + (size_t)row * KDIM;
    __nv_bfloat16* dst = g_supB + (size_t)row * KPAD;
    float s = 0.f;
    for (int k = lane; k < KDIM; k += 32) {
        __nv_bfloat16 b = __float2bfloat16(src[k]);
        dst[k] = b;
        float v = __bfloat162float(b);
        s += v * v;
    }
    if (lane < KPAD - KDIM) dst[KDIM + lane] = __float2bfloat16(0.f);
    #pragma unroll
    for (int off = 16; off; off >>= 1) s += __shfl_xor_sync(0xffffffffu, s, off);
    if (lane == 0) g_s2[row] = s;
}

// ---------------------------------------------------------------------------
// bf16 mma.sync fused GEMM (R5 config: 128x128, 256 thr, 3-stage, 2 CTA/SM)
// with ONE __syncthreads per stage: the arrival at stage s's sync proves all
// threads finished stage s-1's ldmatrix reads, so prefetch(s+2) into buffer
// (s+2)%3 == (s-1)%3 after the sync is race-free.
// ---------------------------------------------------------------------------
__global__ void __launch_bounds__(256, 2) gemm_mma(const float* __restrict__ alpha)
{
    extern __shared__ char dsm[];
    float* s2s = (float*)(dsm + OFF_S2);
    float* f2s = (float*)(dsm + OFF_F2);
    float4* als = (float4*)(dsm + OFF_AL);
    float* red = (float*)(dsm + OFF_A);   // reused after mainloop

    const int tid = threadIdx.x;
    const int lane = tid & 31, wid = tid >> 5;
    const int wi = wid >> 2;        // 0..1 : 64-row slice
    const int wj = wid & 3;         // 0..3 : 32-col slice
    const int ibase = blockIdx.x * TI;
    const int jbase = blockIdx.y * TJ;

    if (tid < TI) f2s[tid] = g_f2[ibase + tid];
    if (tid < TJ) {
        s2s[tid] = g_s2[jbase + tid];
        als[tid] = ((const float4*)alpha)[jbase + tid];
    }

    uint32_t aBase[3], bBase[3];
    #pragma unroll
    for (int b = 0; b < 3; b++) {
        aBase[b] = smem_u32(dsm + OFF_A + b * TI * STA * 2);
        bBase[b] = smem_u32(dsm + OFF_B + b * TJ * STA * 2);
    }
    const __nv_bfloat16* gA = g_featsB + (size_t)ibase * KPAD;
    const __nv_bfloat16* gB = g_supB + (size_t)jbase * KPAD;

    float acc[4][4][4];
    #pragma unroll
    for (int mi = 0; mi < 4; mi++)
        #pragma unroll
        for (int nj = 0; nj < 4; nj++)
            #pragma unroll
            for (int e = 0; e < 4; e++) acc[mi][nj][e] = 0.f;

    auto prefetch = [&](int s, int b) {
        #pragma unroll
        for (int tcnt = 0; tcnt < 2; tcnt++) {
            int id = tid + tcnt * 256;
            int r = id >> 2, c = id & 3;
            cp16(aBase[b] + (r * STA + c * 8) * 2, gA + (size_t)r * KPAD + s * KC + c * 8);
        }
        #pragma unroll
        for (int tcnt = 0; tcnt < 2; tcnt++) {
            int id = tid + tcnt * 256;
            int r = id >> 2, c = id & 3;
            cp16(bBase[b] + (r * STA + c * 8) * 2, gB + (size_t)r * KPAD + s * KC + c * 8);
        }
        asm volatile("cp.async.commit_group;" ::: "memory");
    };

    prefetch(0, 0);
    prefetch(1, 1);

    const int a_row = (lane & 15);
    const int a_koff = (lane >> 4) * 8;
    const int b_nrow = ((lane >> 4) & 1) * 8 + (lane & 7);
    const int b_koff = ((lane >> 3) & 1) * 8;

    for (int s = 0; s < NSTAGE; s++) {
        if (s + 1 < NSTAGE) {
            asm volatile("cp.async.wait_group 1;" ::: "memory");
        } else {
            asm volatile("cp.async.wait_group 0;" ::: "memory");
        }
        __syncthreads();
        if (s + 2 < NSTAGE) prefetch(s + 2, (s + 2) % 3);

        const int b = s % 3;
        #pragma unroll
        for (int ks = 0; ks < 2; ks++) {
            uint32_t afr[4][4];
            #pragma unroll
            for (int mi = 0; mi < 4; mi++) {
                uint32_t addr = aBase[b] +
                    ((wi * 64 + mi * 16 + a_row) * STA + ks * 16 + a_koff) * 2;
                ldm_x4(afr[mi], addr);
            }
            uint32_t bfr[2][4];
            #pragma unroll
            for (int njp = 0; njp < 2; njp++) {
                uint32_t addr = bBase[b] +
                    ((wj * 32 + njp * 16 + b_nrow) * STA + ks * 16 + b_koff) * 2;
                ldm_x4(bfr[njp], addr);
            }
            #pragma unroll
            for (int mi = 0; mi < 4; mi++)
                #pragma unroll
                for (int nj = 0; nj < 4; nj++)
                    mma_bf16(acc[mi][nj], afr[mi],
                             bfr[nj >> 1][(nj & 1) * 2 + 0],
                             bfr[nj >> 1][(nj & 1) * 2 + 1]);
        }
    }

    // ---------------- epilogue: RBF + alpha, fused ----------------
    const int r0 = lane >> 2;
    const int c0 = (lane & 3) * 2;
    float po[8][4];
    #pragma unroll
    for (int i = 0; i < 8; i++)
        #pragma unroll
        for (int c = 0; c < 4; c++) po[i][c] = 0.f;

    #pragma unroll
    for (int mi = 0; mi < 4; mi++)
        #pragma unroll
        for (int nj = 0; nj < 4; nj++)
            #pragma unroll
            for (int e = 0; e < 4; e++) {
                int h = e >> 1;
                int rowl = wi * 64 + mi * 16 + r0 + h * 8;
                int coll = wj * 32 + nj * 8 + c0 + (e & 1);
                float d2 = f2s[rowl] + s2s[coll] - 2.0f * acc[mi][nj][e];
                float kv = __expf(-GAMMA * d2);
                float4 al = als[coll];
                po[mi * 2 + h][0] += kv * al.x;
                po[mi * 2 + h][1] += kv * al.y;
                po[mi * 2 + h][2] += kv * al.z;
                po[mi * 2 + h][3] += kv * al.w;
            }

    #pragma unroll
    for (int off = 1; off <= 2; off <<= 1)
        #pragma unroll
        for (int i = 0; i < 8; i++)
            #pragma unroll
            for (int c = 0; c < 4; c++)
                po[i][c] += __shfl_xor_sync(0xffffffffu, po[i][c], off);

    __syncthreads();   // all ldmatrix reads done before red overwrites buf 0

    if ((lane & 3) == 0) {
        #pragma unroll
        for (int i = 0; i < 8; i++) {
            int mi = i >> 1, h = i & 1;
            int rowl = wi * 64 + mi * 16 + r0 + h * 8;
            #pragma unroll
            for (int c = 0; c < 4; c++)
                red[(wj * TI + rowl) * 4 + c] = po[i][c];
        }
    }
    __syncthreads();

    for (int id = tid; id < TI * NCLS; id += 256) {
        int rowl = id >> 2, c = id & 3;
        float sum = red[(0 * TI + rowl) * 4 + c] + red[(1 * TI + rowl) * 4 + c]
                  + red[(2 * TI + rowl) * 4 + c] + red[(3 * TI + rowl) * 4 + c];
        g_part[(size_t)blockIdx.y * NIMG * NCLS + (size_t)(ibase + rowl) * NCLS + c] = sum;
    }
}

// ---------------------------------------------------------------------------
// combine: 16 lanes per output element, 4 partials each, shfl-tree reduce.
// 1024 blocks -> latency-hiding parallelism (old version: 64 blocks, 9.4us).
// ---------------------------------------------------------------------------
__global__ void __launch_bounds__(256) combine_kernel(float* __restrict__ out)
{
    const int tid = threadIdx.x;
    const int i = blockIdx.x * 16 + (tid >> 4);    // output element
    const int sub = tid & 15;                      // partial slice
    float s = 0.f;
    #pragma unroll
    for (int q = 0; q < 4; q++)
        s += g_part[(size_t)(sub + q * 16) * NIMG * NCLS + i];
    #pragma unroll
    for (int off = 8; off; off >>= 1) s += __shfl_xor_sync(0xffffffffu, s, off);
    if (sub == 0) out[i] = s;
}

// ---------------------------------------------------------------------------
extern "C" void kernel_launch(void* const* d_in, const int* in_sizes, int n_in,
                              void* d_out, int out_size)
{
    const float* x       = (const float*)d_in[0];
    const float* w1      = (const float*)d_in[1];
    const float* b1      = (const float*)d_in[2];
    const float* w2      = (const float*)d_in[3];
    const float* b2      = (const float*)d_in[4];
    const float* support = (const float*)d_in[5];
    const float* alpha   = (const float*)d_in[6];
    float* out = (float*)d_out;

    static bool attr_set = false;
    if (!attr_set) {
        cudaFuncSetAttribute(gemm_mma, cudaFuncAttributeMaxDynamicSharedMemorySize, GEMM_SMEM);
        attr_set = true;
    }

    conv_kernel<<<NIMG / 2, 256>>>(x, w1, b1, w2, b2);
    prep_support<<<MSUP / 8, 256>>>(support);
    gemm_mma<<<dim3(NIT, NJT), 256, GEMM_SMEM>>>(alpha);
    combine_kernel<<<NIMG * NCLS / 16, 256>>>(out);
}

// round 8
// speedup vs baseline: 1.1431x; 1.0074x over previous
#include <cuda_runtime.h>
#include <cuda_bf16.h>
#include <cstdint>

#define GAMMA 0.001f
#define NIMG 4096
#define MSUP 8192
#define KDIM 784
#define KPAD 800
#define NCLS 4

#define TI 128
#define TJ 128
#define KC 32
#define STA 40                 // padded smem row stride (elems): 80B, conflict-free
#define NSTAGE (KPAD / KC)     // 25
#define NJT (MSUP / TJ)        // 64
#define NIT (NIMG / TI)        // 32

#define CONV_BLOCKS (NIMG / 2)     // 2048
#define PREP_BLOCKS (MSUP / 8)     // 1024

// ---- gemm dynamic smem layout (bytes) ----
#define OFF_A 0                          // 3 x TI*STA bf16 = 30720
#define OFF_B 30720                      // 3 x TJ*STA bf16 = 30720
#define OFF_S2 61440                     // 512
#define OFF_F2 61952                     // 512
#define OFF_AL 62464                     // 2048
#define GEMM_SMEM 64512

// ---- device scratch (no allocs allowed) ----
__device__ __nv_bfloat16 g_featsB[NIMG * KPAD];
__device__ __nv_bfloat16 g_supB[MSUP * KPAD];
__device__ float g_s2[MSUP];
__device__ float g_f2[NIMG];
__device__ float g_part[NJT * NIMG * NCLS];

// ---------------------------------------------------------------------------
__device__ __forceinline__ uint32_t smem_u32(const void* p) {
    uint32_t a;
    asm("{ .reg .u64 t; cvta.to.shared.u64 t, %1; cvt.u32.u64 %0, t; }" : "=r"(a) : "l"(p));
    return a;
}
__device__ __forceinline__ void cp16(uint32_t smem, const void* gmem) {
    asm volatile("cp.async.cg.shared.global [%0], [%1], 16;" :: "r"(smem), "l"(gmem));
}
__device__ __forceinline__ void ldm_x4(uint32_t* r, uint32_t addr) {
    asm volatile("ldmatrix.sync.aligned.m8n8.x4.shared.b16 {%0,%1,%2,%3}, [%4];"
                 : "=r"(r[0]), "=r"(r[1]), "=r"(r[2]), "=r"(r[3]) : "r"(addr));
}
__device__ __forceinline__ void mma_bf16(float* d, const uint32_t* a, uint32_t b0, uint32_t b1) {
    asm volatile(
        "mma.sync.aligned.m16n8k16.row.col.f32.bf16.bf16.f32 "
        "{%0,%1,%2,%3}, {%4,%5,%6,%7}, {%8,%9}, {%0,%1,%2,%3};"
        : "+f"(d[0]), "+f"(d[1]), "+f"(d[2]), "+f"(d[3])
        : "r"(a[0]), "r"(a[1]), "r"(a[2]), "r"(a[3]), "r"(b0), "r"(b1));
}

// ---------------------------------------------------------------------------
// Merged preprocessing launch:
//   blocks [0, CONV_BLOCKS)                : conv pipeline (2 images/block)
//   blocks [CONV_BLOCKS, +PREP_BLOCKS)     : support bf16 conversion + s2
// Independent work; prep hides inside conv's duration.
// ---------------------------------------------------------------------------
__global__ void __launch_bounds__(256) pre_kernel(
    const float* __restrict__ x,
    const float* __restrict__ w1, const float* __restrict__ b1,
    const float* __restrict__ w2, const float* __restrict__ b2,
    const float* __restrict__ support)
{
    const int tid = threadIdx.x;

    if (blockIdx.x >= CONV_BLOCKS) {
        // ---------------- prep_support path ----------------
        int row = (blockIdx.x - CONV_BLOCKS) * 8 + (tid >> 5);
        int lane = tid & 31;
        const float* src = support + (size_t)row * KDIM;
        __nv_bfloat16* dst = g_supB + (size_t)row * KPAD;
        float s = 0.f;
        for (int k = lane; k < KDIM; k += 32) {
            __nv_bfloat16 b = __float2bfloat16(src[k]);
            dst[k] = b;
            float v = __bfloat162float(b);
            s += v * v;
        }
        if (lane < KPAD - KDIM) dst[KDIM + lane] = __float2bfloat16(0.f);
        #pragma unroll
        for (int off = 16; off; off >>= 1) s += __shfl_xor_sync(0xffffffffu, s, off);
        if (lane == 0) g_s2[row] = s;
        return;
    }

    // ---------------- conv path (R5-proven) ----------------
    __shared__ float sx[2][900];          // 30x30 padded (+1)
    __shared__ float sp1[2][2048];        // 8 x 16x16 padded (+1)
    __shared__ float sw1[72], sb1[8], sw2[1152], sb2[16];
    __shared__ float sred[2][4];

    const int img = tid >> 7;
    const int t = tid & 127;
    const int n = blockIdx.x * 2 + img;

    for (int i = tid; i < 1800; i += 256) ((float*)sx)[i] = 0.f;
    for (int i = tid; i < 4096; i += 256) ((float*)sp1)[i] = 0.f;
    for (int i = tid; i < 72; i += 256) sw1[i] = w1[i];
    if (tid < 8) sb1[tid] = b1[tid];
    for (int i = tid; i < 1152; i += 256) sw2[i] = w2[i];
    if (tid < 16) sb2[tid] = b2[tid];
    __syncthreads();

    const float* xn = x + (size_t)n * 784;
    for (int i = t; i < 784; i += 128) {
        int yy = i / 28, xx = i % 28;
        sx[img][(yy + 1) * 30 + xx + 1] = xn[i];
    }
    __syncthreads();

    // ---- conv1 + relu + pool: thread = (c in 0..7, px in 0..13) ----
    if (t < 112) {
        const int c = t & 7, px = t >> 3;
        float w[9];
        #pragma unroll
        for (int k = 0; k < 9; k++) w[k] = sw1[c * 9 + k];
        const float bb = sb1[c];
        const float* sxi = sx[img];
        float W[4][4];
        #pragma unroll
        for (int py = 0; py < 14; py++) {
            if (py == 0) {
                #pragma unroll
                for (int r = 0; r < 4; r++)
                    #pragma unroll
                    for (int cc = 0; cc < 4; cc++)
                        W[r][cc] = sxi[r * 30 + 2 * px + cc];
            } else {
                #pragma unroll
                for (int cc = 0; cc < 4; cc++) { W[0][cc] = W[2][cc]; W[1][cc] = W[3][cc]; }
                #pragma unroll
                for (int r = 2; r < 4; r++)
                    #pragma unroll
                    for (int cc = 0; cc < 4; cc++)
                        W[r][cc] = sxi[(2 * py + r) * 30 + 2 * px + cc];
            }
            float m = 0.f;
            #pragma unroll
            for (int sy = 0; sy < 2; sy++)
                #pragma unroll
                for (int sxx = 0; sxx < 2; sxx++) {
                    float acc = bb;
                    #pragma unroll
                    for (int dy = 0; dy < 3; dy++)
                        #pragma unroll
                        for (int dx = 0; dx < 3; dx++)
                            acc += w[dy * 3 + dx] * W[sy + dy][sxx + dx];
                    m = fmaxf(m, fmaxf(acc, 0.f));
                }
            sp1[img][c * 256 + (py + 1) * 16 + px + 1] = m;
        }
    }
    __syncthreads();

    // ---- conv2 + relu + pool: thread = (c in 0..15, px in 0..6) ----
    float sq = 0.f;
    if (t < 112) {
        const int px = t % 7, c = t / 7;
        float acc[7][4];
        const float bb = sb2[c];
        #pragma unroll
        for (int py = 0; py < 7; py++)
            #pragma unroll
            for (int q = 0; q < 4; q++) acc[py][q] = bb;

        #pragma unroll
        for (int ic = 0; ic < 8; ic++) {
            float w[9];
            #pragma unroll
            for (int k = 0; k < 9; k++) w[k] = sw2[c * 72 + ic * 9 + k];
            const float* sp = sp1[img] + ic * 256;
            float W[4][4];
            #pragma unroll
            for (int py = 0; py < 7; py++) {
                if (py == 0) {
                    #pragma unroll
                    for (int r = 0; r < 4; r++)
                        #pragma unroll
                        for (int cc = 0; cc < 4; cc++)
                            W[r][cc] = sp[r * 16 + 2 * px + cc];
                } else {
                    #pragma unroll
                    for (int cc = 0; cc < 4; cc++) { W[0][cc] = W[2][cc]; W[1][cc] = W[3][cc]; }
                    #pragma unroll
                    for (int r = 2; r < 4; r++)
                        #pragma unroll
                        for (int cc = 0; cc < 4; cc++)
                            W[r][cc] = sp[(2 * py + r) * 16 + 2 * px + cc];
                }
                #pragma unroll
                for (int sy = 0; sy < 2; sy++)
                    #pragma unroll
                    for (int sxx = 0; sxx < 2; sxx++) {
                        float a2 = 0.f;
                        #pragma unroll
                        for (int dy = 0; dy < 3; dy++)
                            #pragma unroll
                            for (int dx = 0; dx < 3; dx++)
                                a2 += w[dy * 3 + dx] * W[sy + dy][sxx + dx];
                        acc[py][sy * 2 + sxx] += a2;
                    }
            }
        }
        __nv_bfloat16* fdst = g_featsB + (size_t)n * KPAD + c * 49 + px;
        #pragma unroll
        for (int py = 0; py < 7; py++) {
            float m = 0.f;
            #pragma unroll
            for (int q = 0; q < 4; q++) m = fmaxf(m, fmaxf(acc[py][q], 0.f));
            __nv_bfloat16 bv = __float2bfloat16(m);
            fdst[py * 7] = bv;
            float fv = __bfloat162float(bv);
            sq += fv * fv;
        }
    }
    if (t < KPAD - KDIM)
        g_featsB[(size_t)n * KPAD + KDIM + t] = __float2bfloat16(0.f);

    // f2 block reduction (per image: 4 warps)
    #pragma unroll
    for (int off = 16; off; off >>= 1) sq += __shfl_xor_sync(0xffffffffu, sq, off);
    if ((t & 31) == 0) sred[img][(t >> 5) & 3] = sq;
    __syncthreads();
    if (t == 0) g_f2[n] = sred[img][0] + sred[img][1] + sred[img][2] + sred[img][3];
}

// ---------------------------------------------------------------------------
// bf16 mma.sync fused GEMM (128x128, 256 thr, 3-stage, 2 CTA/SM), stage body
// reordered for ILP: B-frags of BOTH k-halves issued before ks0's MMA block,
// so the ks1 MMA group never waits on a just-issued LDSM.
// ---------------------------------------------------------------------------
__global__ void __launch_bounds__(256, 2) gemm_mma(const float* __restrict__ alpha)
{
    extern __shared__ char dsm[];
    float* s2s = (float*)(dsm + OFF_S2);
    float* f2s = (float*)(dsm + OFF_F2);
    float4* als = (float4*)(dsm + OFF_AL);
    float* red = (float*)(dsm + OFF_A);   // reused after mainloop

    const int tid = threadIdx.x;
    const int lane = tid & 31, wid = tid >> 5;
    const int wi = wid >> 2;        // 0..1 : 64-row slice
    const int wj = wid & 3;         // 0..3 : 32-col slice
    const int ibase = blockIdx.x * TI;
    const int jbase = blockIdx.y * TJ;

    if (tid < TI) f2s[tid] = g_f2[ibase + tid];
    if (tid < TJ) {
        s2s[tid] = g_s2[jbase + tid];
        als[tid] = ((const float4*)alpha)[jbase + tid];
    }

    uint32_t aBase[3], bBase[3];
    #pragma unroll
    for (int b = 0; b < 3; b++) {
        aBase[b] = smem_u32(dsm + OFF_A + b * TI * STA * 2);
        bBase[b] = smem_u32(dsm + OFF_B + b * TJ * STA * 2);
    }
    const __nv_bfloat16* gA = g_featsB + (size_t)ibase * KPAD;
    const __nv_bfloat16* gB = g_supB + (size_t)jbase * KPAD;

    float acc[4][4][4];
    #pragma unroll
    for (int mi = 0; mi < 4; mi++)
        #pragma unroll
        for (int nj = 0; nj < 4; nj++)
            #pragma unroll
            for (int e = 0; e < 4; e++) acc[mi][nj][e] = 0.f;

    auto prefetch = [&](int s, int b) {
        #pragma unroll
        for (int tcnt = 0; tcnt < 2; tcnt++) {
            int id = tid + tcnt * 256;
            int r = id >> 2, c = id & 3;
            cp16(aBase[b] + (r * STA + c * 8) * 2, gA + (size_t)r * KPAD + s * KC + c * 8);
        }
        #pragma unroll
        for (int tcnt = 0; tcnt < 2; tcnt++) {
            int id = tid + tcnt * 256;
            int r = id >> 2, c = id & 3;
            cp16(bBase[b] + (r * STA + c * 8) * 2, gB + (size_t)r * KPAD + s * KC + c * 8);
        }
        asm volatile("cp.async.commit_group;" ::: "memory");
    };

    prefetch(0, 0);
    prefetch(1, 1);

    const int a_row = (lane & 15);
    const int a_koff = (lane >> 4) * 8;
    const int b_nrow = ((lane >> 4) & 1) * 8 + (lane & 7);
    const int b_koff = ((lane >> 3) & 1) * 8;

    for (int s = 0; s < NSTAGE; s++) {
        if (s + 1 < NSTAGE) {
            asm volatile("cp.async.wait_group 1;" ::: "memory");
        } else {
            asm volatile("cp.async.wait_group 0;" ::: "memory");
        }
        __syncthreads();
        if (s + 2 < NSTAGE) prefetch(s + 2, (s + 2) % 3);

        const int b = s % 3;

        // ---- reordered stage body: all ks0 frags + ks1 B frags first ----
        uint32_t afr0[4][4], afr1[4][4];
        uint32_t bfr0[2][4], bfr1[2][4];
        #pragma unroll
        for (int mi = 0; mi < 4; mi++)
            ldm_x4(afr0[mi], aBase[b] + ((wi * 64 + mi * 16 + a_row) * STA + a_koff) * 2);
        #pragma unroll
        for (int njp = 0; njp < 2; njp++)
            ldm_x4(bfr0[njp], bBase[b] + ((wj * 32 + njp * 16 + b_nrow) * STA + b_koff) * 2);
        #pragma unroll
        for (int njp = 0; njp < 2; njp++)
            ldm_x4(bfr1[njp], bBase[b] + ((wj * 32 + njp * 16 + b_nrow) * STA + 16 + b_koff) * 2);

        #pragma unroll
        for (int mi = 0; mi < 4; mi++)
            #pragma unroll
            for (int nj = 0; nj < 4; nj++)
                mma_bf16(acc[mi][nj], afr0[mi],
                         bfr0[nj >> 1][(nj & 1) * 2 + 0],
                         bfr0[nj >> 1][(nj & 1) * 2 + 1]);

        #pragma unroll
        for (int mi = 0; mi < 4; mi++)
            ldm_x4(afr1[mi], aBase[b] + ((wi * 64 + mi * 16 + a_row) * STA + 16 + a_koff) * 2);

        #pragma unroll
        for (int mi = 0; mi < 4; mi++)
            #pragma unroll
            for (int nj = 0; nj < 4; nj++)
                mma_bf16(acc[mi][nj], afr1[mi],
                         bfr1[nj >> 1][(nj & 1) * 2 + 0],
                         bfr1[nj >> 1][(nj & 1) * 2 + 1]);
    }

    // ---------------- epilogue: RBF + alpha, fused ----------------
    const int r0 = lane >> 2;
    const int c0 = (lane & 3) * 2;
    float po[8][4];
    #pragma unroll
    for (int i = 0; i < 8; i++)
        #pragma unroll
        for (int c = 0; c < 4; c++) po[i][c] = 0.f;

    #pragma unroll
    for (int mi = 0; mi < 4; mi++)
        #pragma unroll
        for (int nj = 0; nj < 4; nj++)
            #pragma unroll
            for (int e = 0; e < 4; e++) {
                int h = e >> 1;
                int rowl = wi * 64 + mi * 16 + r0 + h * 8;
                int coll = wj * 32 + nj * 8 + c0 + (e & 1);
                float d2 = f2s[rowl] + s2s[coll] - 2.0f * acc[mi][nj][e];
                float kv = __expf(-GAMMA * d2);
                float4 al = als[coll];
                po[mi * 2 + h][0] += kv * al.x;
                po[mi * 2 + h][1] += kv * al.y;
                po[mi * 2 + h][2] += kv * al.z;
                po[mi * 2 + h][3] += kv * al.w;
            }

    #pragma unroll
    for (int off = 1; off <= 2; off <<= 1)
        #pragma unroll
        for (int i = 0; i < 8; i++)
            #pragma unroll
            for (int c = 0; c < 4; c++)
                po[i][c] += __shfl_xor_sync(0xffffffffu, po[i][c], off);

    __syncthreads();   // all ldmatrix reads done before red overwrites buf 0

    if ((lane & 3) == 0) {
        #pragma unroll
        for (int i = 0; i < 8; i++) {
            int mi = i >> 1, h = i & 1;
            int rowl = wi * 64 + mi * 16 + r0 + h * 8;
            #pragma unroll
            for (int c = 0; c < 4; c++)
                red[(wj * TI + rowl) * 4 + c] = po[i][c];
        }
    }
    __syncthreads();

    for (int id = tid; id < TI * NCLS; id += 256) {
        int rowl = id >> 2, c = id & 3;
        float sum = red[(0 * TI + rowl) * 4 + c] + red[(1 * TI + rowl) * 4 + c]
                  + red[(2 * TI + rowl) * 4 + c] + red[(3 * TI + rowl) * 4 + c];
        g_part[(size_t)blockIdx.y * NIMG * NCLS + (size_t)(ibase + rowl) * NCLS + c] = sum;
    }
}

// ---------------------------------------------------------------------------
// combine: 16 lanes per output element, 4 partials each, shfl-tree reduce.
// ---------------------------------------------------------------------------
__global__ void __launch_bounds__(256) combine_kernel(float* __restrict__ out)
{
    const int tid = threadIdx.x;
    const int i = blockIdx.x * 16 + (tid >> 4);    // output element
    const int sub = tid & 15;                      // partial slice
    float s = 0.f;
    #pragma unroll
    for (int q = 0; q < 4; q++)
        s += g_part[(size_t)(sub + q * 16) * NIMG * NCLS + i];
    #pragma unroll
    for (int off = 8; off; off >>= 1) s += __shfl_xor_sync(0xffffffffu, s, off);
    if (sub == 0) out[i] = s;
}

// ---------------------------------------------------------------------------
extern "C" void kernel_launch(void* const* d_in, const int* in_sizes, int n_in,
                              void* d_out, int out_size)
{
    const float* x       = (const float*)d_in[0];
    const float* w1      = (const float*)d_in[1];
    const float* b1      = (const float*)d_in[2];
    const float* w2      = (const float*)d_in[3];
    const float* b2      = (const float*)d_in[4];
    const float* support = (const float*)d_in[5];
    const float* alpha   = (const float*)d_in[6];
    float* out = (float*)d_out;

    static bool attr_set = false;
    if (!attr_set) {
        cudaFuncSetAttribute(gemm_mma, cudaFuncAttributeMaxDynamicSharedMemorySize, GEMM_SMEM);
        attr_set = true;
    }

    pre_kernel<<<CONV_BLOCKS + PREP_BLOCKS, 256>>>(x, w1, b1, w2, b2, support);
    gemm_mma<<<dim3(NIT, NJT), 256, GEMM_SMEM>>>(alpha);
    combine_kernel<<<NIMG * NCLS / 16, 256>>>(out);
}

// round 9
// speedup vs baseline: 1.2095x; 1.0581x over previous
#include <cuda_runtime.h>
#include <cuda_bf16.h>
#include <cstdint>

#define GAMMA 0.001f
#define NIMG 4096
#define MSUP 8192
#define KDIM 784
#define KPAD 800
#define NCLS 4

#define TI 128
#define TJ 128
#define KC 80
#define STA 88                 // padded smem row stride (elems): 176B, conflict-free
#define NSTAGE (KPAD / KC)     // 10
#define NJT (MSUP / TJ)        // 64
#define NIT (NIMG / TI)        // 32

#define CONV_BLOCKS (NIMG / 2)     // 2048
#define PREP_BLOCKS (MSUP / 8)     // 1024

// ---- gemm dynamic smem layout (bytes) ----
#define BUF_BYTES (TI * STA * 2)         // 22528 per tile per buffer
#define OFF_A 0                          // 2 x 22528 = 45056
#define OFF_B 45056                      // 2 x 22528 = 45056
#define OFF_S2 90112                     // 512
#define OFF_F2 90624                     // 512
#define OFF_AL 91136                     // 2048
#define GEMM_SMEM 93184

// ---- device scratch (no allocs allowed) ----
__device__ __nv_bfloat16 g_featsB[NIMG * KPAD];
__device__ __nv_bfloat16 g_supB[MSUP * KPAD];
__device__ float g_s2[MSUP];
__device__ float g_f2[NIMG];
__device__ float g_part[NJT * NIMG * NCLS];

// ---------------------------------------------------------------------------
__device__ __forceinline__ uint32_t smem_u32(const void* p) {
    uint32_t a;
    asm("{ .reg .u64 t; cvta.to.shared.u64 t, %1; cvt.u32.u64 %0, t; }" : "=r"(a) : "l"(p));
    return a;
}
__device__ __forceinline__ void cp16(uint32_t smem, const void* gmem) {
    asm volatile("cp.async.cg.shared.global [%0], [%1], 16;" :: "r"(smem), "l"(gmem));
}
__device__ __forceinline__ void ldm_x4(uint32_t* r, uint32_t addr) {
    asm volatile("ldmatrix.sync.aligned.m8n8.x4.shared.b16 {%0,%1,%2,%3}, [%4];"
                 : "=r"(r[0]), "=r"(r[1]), "=r"(r[2]), "=r"(r[3]) : "r"(addr));
}
__device__ __forceinline__ void mma_bf16(float* d, const uint32_t* a, uint32_t b0, uint32_t b1) {
    asm volatile(
        "mma.sync.aligned.m16n8k16.row.col.f32.bf16.bf16.f32 "
        "{%0,%1,%2,%3}, {%4,%5,%6,%7}, {%8,%9}, {%0,%1,%2,%3};"
        : "+f"(d[0]), "+f"(d[1]), "+f"(d[2]), "+f"(d[3])
        : "r"(a[0]), "r"(a[1]), "r"(a[2]), "r"(a[3]), "r"(b0), "r"(b1));
}

// ---------------------------------------------------------------------------
// Merged preprocessing launch:
//   blocks [0, CONV_BLOCKS)                : conv pipeline (2 images/block)
//   blocks [CONV_BLOCKS, +PREP_BLOCKS)     : support bf16 conversion + s2
// ---------------------------------------------------------------------------
__global__ void __launch_bounds__(256) pre_kernel(
    const float* __restrict__ x,
    const float* __restrict__ w1, const float* __restrict__ b1,
    const float* __restrict__ w2, const float* __restrict__ b2,
    const float* __restrict__ support)
{
    const int tid = threadIdx.x;

    if (blockIdx.x >= CONV_BLOCKS) {
        int row = (blockIdx.x - CONV_BLOCKS) * 8 + (tid >> 5);
        int lane = tid & 31;
        const float* src = support + (size_t)row * KDIM;
        __nv_bfloat16* dst = g_supB + (size_t)row * KPAD;
        float s = 0.f;
        for (int k = lane; k < KDIM; k += 32) {
            __nv_bfloat16 b = __float2bfloat16(src[k]);
            dst[k] = b;
            float v = __bfloat162float(b);
            s += v * v;
        }
        if (lane < KPAD - KDIM) dst[KDIM + lane] = __float2bfloat16(0.f);
        #pragma unroll
        for (int off = 16; off; off >>= 1) s += __shfl_xor_sync(0xffffffffu, s, off);
        if (lane == 0) g_s2[row] = s;
        return;
    }

    __shared__ float sx[2][900];
    __shared__ float sp1[2][2048];
    __shared__ float sw1[72], sb1[8], sw2[1152], sb2[16];
    __shared__ float sred[2][4];

    const int img = tid >> 7;
    const int t = tid & 127;
    const int n = blockIdx.x * 2 + img;

    for (int i = tid; i < 1800; i += 256) ((float*)sx)[i] = 0.f;
    for (int i = tid; i < 4096; i += 256) ((float*)sp1)[i] = 0.f;
    for (int i = tid; i < 72; i += 256) sw1[i] = w1[i];
    if (tid < 8) sb1[tid] = b1[tid];
    for (int i = tid; i < 1152; i += 256) sw2[i] = w2[i];
    if (tid < 16) sb2[tid] = b2[tid];
    __syncthreads();

    const float* xn = x + (size_t)n * 784;
    for (int i = t; i < 784; i += 128) {
        int yy = i / 28, xx = i % 28;
        sx[img][(yy + 1) * 30 + xx + 1] = xn[i];
    }
    __syncthreads();

    if (t < 112) {
        const int c = t & 7, px = t >> 3;
        float w[9];
        #pragma unroll
        for (int k = 0; k < 9; k++) w[k] = sw1[c * 9 + k];
        const float bb = sb1[c];
        const float* sxi = sx[img];
        float W[4][4];
        #pragma unroll
        for (int py = 0; py < 14; py++) {
            if (py == 0) {
                #pragma unroll
                for (int r = 0; r < 4; r++)
                    #pragma unroll
                    for (int cc = 0; cc < 4; cc++)
                        W[r][cc] = sxi[r * 30 + 2 * px + cc];
            } else {
                #pragma unroll
                for (int cc = 0; cc < 4; cc++) { W[0][cc] = W[2][cc]; W[1][cc] = W[3][cc]; }
                #pragma unroll
                for (int r = 2; r < 4; r++)
                    #pragma unroll
                    for (int cc = 0; cc < 4; cc++)
                        W[r][cc] = sxi[(2 * py + r) * 30 + 2 * px + cc];
            }
            float m = 0.f;
            #pragma unroll
            for (int sy = 0; sy < 2; sy++)
                #pragma unroll
                for (int sxx = 0; sxx < 2; sxx++) {
                    float acc = bb;
                    #pragma unroll
                    for (int dy = 0; dy < 3; dy++)
                        #pragma unroll
                        for (int dx = 0; dx < 3; dx++)
                            acc += w[dy * 3 + dx] * W[sy + dy][sxx + dx];
                    m = fmaxf(m, fmaxf(acc, 0.f));
                }
            sp1[img][c * 256 + (py + 1) * 16 + px + 1] = m;
        }
    }
    __syncthreads();

    float sq = 0.f;
    if (t < 112) {
        const int px = t % 7, c = t / 7;
        float acc[7][4];
        const float bb = sb2[c];
        #pragma unroll
        for (int py = 0; py < 7; py++)
            #pragma unroll
            for (int q = 0; q < 4; q++) acc[py][q] = bb;

        #pragma unroll
        for (int ic = 0; ic < 8; ic++) {
            float w[9];
            #pragma unroll
            for (int k = 0; k < 9; k++) w[k] = sw2[c * 72 + ic * 9 + k];
            const float* sp = sp1[img] + ic * 256;
            float W[4][4];
            #pragma unroll
            for (int py = 0; py < 7; py++) {
                if (py == 0) {
                    #pragma unroll
                    for (int r = 0; r < 4; r++)
                        #pragma unroll
                        for (int cc = 0; cc < 4; cc++)
                            W[r][cc] = sp[r * 16 + 2 * px + cc];
                } else {
                    #pragma unroll
                    for (int cc = 0; cc < 4; cc++) { W[0][cc] = W[2][cc]; W[1][cc] = W[3][cc]; }
                    #pragma unroll
                    for (int r = 2; r < 4; r++)
                        #pragma unroll
                        for (int cc = 0; cc < 4; cc++)
                            W[r][cc] = sp[(2 * py + r) * 16 + 2 * px + cc];
                }
                #pragma unroll
                for (int sy = 0; sy < 2; sy++)
                    #pragma unroll
                    for (int sxx = 0; sxx < 2; sxx++) {
                        float a2 = 0.f;
                        #pragma unroll
                        for (int dy = 0; dy < 3; dy++)
                            #pragma unroll
                            for (int dx = 0; dx < 3; dx++)
                                a2 += w[dy * 3 + dx] * W[sy + dy][sxx + dx];
                        acc[py][sy * 2 + sxx] += a2;
                    }
            }
        }
        __nv_bfloat16* fdst = g_featsB + (size_t)n * KPAD + c * 49 + px;
        #pragma unroll
        for (int py = 0; py < 7; py++) {
            float m = 0.f;
            #pragma unroll
            for (int q = 0; q < 4; q++) m = fmaxf(m, fmaxf(acc[py][q], 0.f));
            __nv_bfloat16 bv = __float2bfloat16(m);
            fdst[py * 7] = bv;
            float fv = __bfloat162float(bv);
            sq += fv * fv;
        }
    }
    if (t < KPAD - KDIM)
        g_featsB[(size_t)n * KPAD + KDIM + t] = __float2bfloat16(0.f);

    #pragma unroll
    for (int off = 16; off; off >>= 1) sq += __shfl_xor_sync(0xffffffffu, sq, off);
    if ((t & 31) == 0) sred[img][(t >> 5) & 3] = sq;
    __syncthreads();
    if (t == 0) g_f2[n] = sred[img][0] + sred[img][1] + sred[img][2] + sred[img][3];
}

// ---------------------------------------------------------------------------
// bf16 mma.sync fused GEMM: 128x128 CTA tile, KC=80 (10 stages, 2 buffers),
// register double-buffered fragments across the 5 k-halves of each stage.
// One sync + one wait per stage; prefetch(s+1) overlaps stage s compute.
// ---------------------------------------------------------------------------
__global__ void __launch_bounds__(256, 2) gemm_mma(const float* __restrict__ alpha)
{
    extern __shared__ char dsm[];
    float* s2s = (float*)(dsm + OFF_S2);
    float* f2s = (float*)(dsm + OFF_F2);
    float4* als = (float4*)(dsm + OFF_AL);
    float* red = (float*)(dsm + OFF_A);   // reused after mainloop

    const int tid = threadIdx.x;
    const int lane = tid & 31, wid = tid >> 5;
    const int wi = wid >> 2;        // 0..1 : 64-row slice
    const int wj = wid & 3;         // 0..3 : 32-col slice
    const int ibase = blockIdx.x * TI;
    const int jbase = blockIdx.y * TJ;

    if (tid < TI) f2s[tid] = g_f2[ibase + tid];
    if (tid < TJ) {
        s2s[tid] = g_s2[jbase + tid];
        als[tid] = ((const float4*)alpha)[jbase + tid];
    }

    uint32_t aBase[2], bBase[2];
    #pragma unroll
    for (int b = 0; b < 2; b++) {
        aBase[b] = smem_u32(dsm + OFF_A + b * BUF_BYTES);
        bBase[b] = smem_u32(dsm + OFF_B + b * BUF_BYTES);
    }
    const __nv_bfloat16* gA = g_featsB + (size_t)ibase * KPAD;
    const __nv_bfloat16* gB = g_supB + (size_t)jbase * KPAD;

    float acc[4][4][4];
    #pragma unroll
    for (int mi = 0; mi < 4; mi++)
        #pragma unroll
        for (int nj = 0; nj < 4; nj++)
            #pragma unroll
            for (int e = 0; e < 4; e++) acc[mi][nj][e] = 0.f;

    // stage = 80 k-cols: A/B each 128 rows x 10 16B-chunks = 1280 chunks
    auto prefetch = [&](int s, int b) {
        #pragma unroll
        for (int tcnt = 0; tcnt < 5; tcnt++) {
            int id = tid + tcnt * 256;
            int r = id / 10, c = id % 10;
            cp16(aBase[b] + (r * STA + c * 8) * 2, gA + (size_t)r * KPAD + s * KC + c * 8);
        }
        #pragma unroll
        for (int tcnt = 0; tcnt < 5; tcnt++) {
            int id = tid + tcnt * 256;
            int r = id / 10, c = id % 10;
            cp16(bBase[b] + (r * STA + c * 8) * 2, gB + (size_t)r * KPAD + s * KC + c * 8);
        }
        asm volatile("cp.async.commit_group;" ::: "memory");
    };

    prefetch(0, 0);

    const int a_row = (lane & 15);
    const int a_koff = (lane >> 4) * 8;
    const int b_nrow = ((lane >> 4) & 1) * 8 + (lane & 7);
    const int b_koff = ((lane >> 3) & 1) * 8;

    uint32_t afr[2][4][4], bfr[2][2][4];

    for (int s = 0; s < NSTAGE; s++) {
        asm volatile("cp.async.wait_group 0;" ::: "memory");
        __syncthreads();
        if (s + 1 < NSTAGE) prefetch(s + 1, (s + 1) & 1);

        const int b = s & 1;

        // preload k-half 0 into frag slot 0
        #pragma unroll
        for (int mi = 0; mi < 4; mi++)
            ldm_x4(afr[0][mi], aBase[b] + ((wi * 64 + mi * 16 + a_row) * STA + a_koff) * 2);
        #pragma unroll
        for (int njp = 0; njp < 2; njp++)
            ldm_x4(bfr[0][njp], bBase[b] + ((wj * 32 + njp * 16 + b_nrow) * STA + b_koff) * 2);

        #pragma unroll
        for (int kh = 0; kh < 5; kh++) {
            const int cur = kh & 1;
            if (kh < 4) {
                const int nxt = cur ^ 1, ko = (kh + 1) * 16;
                #pragma unroll
                for (int mi = 0; mi < 4; mi++)
                    ldm_x4(afr[nxt][mi],
                           aBase[b] + ((wi * 64 + mi * 16 + a_row) * STA + ko + a_koff) * 2);
                #pragma unroll
                for (int njp = 0; njp < 2; njp++)
                    ldm_x4(bfr[nxt][njp],
                           bBase[b] + ((wj * 32 + njp * 16 + b_nrow) * STA + ko + b_koff) * 2);
            }
            #pragma unroll
            for (int mi = 0; mi < 4; mi++)
                #pragma unroll
                for (int nj = 0; nj < 4; nj++)
                    mma_bf16(acc[mi][nj], afr[cur][mi],
                             bfr[cur][nj >> 1][(nj & 1) * 2 + 0],
                             bfr[cur][nj >> 1][(nj & 1) * 2 + 1]);
        }
    }

    // ---------------- epilogue: RBF + alpha, fused ----------------
    const int r0 = lane >> 2;
    const int c0 = (lane & 3) * 2;
    float po[8][4];
    #pragma unroll
    for (int i = 0; i < 8; i++)
        #pragma unroll
        for (int c = 0; c < 4; c++) po[i][c] = 0.f;

    #pragma unroll
    for (int mi = 0; mi < 4; mi++)
        #pragma unroll
        for (int nj = 0; nj < 4; nj++)
            #pragma unroll
            for (int e = 0; e < 4; e++) {
                int h = e >> 1;
                int rowl = wi * 64 + mi * 16 + r0 + h * 8;
                int coll = wj * 32 + nj * 8 + c0 + (e & 1);
                float d2 = f2s[rowl] + s2s[coll] - 2.0f * acc[mi][nj][e];
                float kv = __expf(-GAMMA * d2);
                float4 al = als[coll];
                po[mi * 2 + h][0] += kv * al.x;
                po[mi * 2 + h][1] += kv * al.y;
                po[mi * 2 + h][2] += kv * al.z;
                po[mi * 2 + h][3] += kv * al.w;
            }

    #pragma unroll
    for (int off = 1; off <= 2; off <<= 1)
        #pragma unroll
        for (int i = 0; i < 8; i++)
            #pragma unroll
            for (int c = 0; c < 4; c++)
                po[i][c] += __shfl_xor_sync(0xffffffffu, po[i][c], off);

    __syncthreads();   // all ldmatrix reads done before red overwrites buf A0

    if ((lane & 3) == 0) {
        #pragma unroll
        for (int i = 0; i < 8; i++) {
            int mi = i >> 1, h = i & 1;
            int rowl = wi * 64 + mi * 16 + r0 + h * 8;
            #pragma unroll
            for (int c = 0; c < 4; c++)
                red[(wj * TI + rowl) * 4 + c] = po[i][c];
        }
    }
    __syncthreads();

    for (int id = tid; id < TI * NCLS; id += 256) {
        int rowl = id >> 2, c = id & 3;
        float sum = red[(0 * TI + rowl) * 4 + c] + red[(1 * TI + rowl) * 4 + c]
                  + red[(2 * TI + rowl) * 4 + c] + red[(3 * TI + rowl) * 4 + c];
        g_part[(size_t)blockIdx.y * NIMG * NCLS + (size_t)(ibase + rowl) * NCLS + c] = sum;
    }
}

// ---------------------------------------------------------------------------
__global__ void __launch_bounds__(256) combine_kernel(float* __restrict__ out)
{
    const int tid = threadIdx.x;
    const int i = blockIdx.x * 16 + (tid >> 4);
    const int sub = tid & 15;
    float s = 0.f;
    #pragma unroll
    for (int q = 0; q < 4; q++)
        s += g_part[(size_t)(sub + q * 16) * NIMG * NCLS + i];
    #pragma unroll
    for (int off = 8; off; off >>= 1) s += __shfl_xor_sync(0xffffffffu, s, off);
    if (sub == 0) out[i] = s;
}

// ---------------------------------------------------------------------------
extern "C" void kernel_launch(void* const* d_in, const int* in_sizes, int n_in,
                              void* d_out, int out_size)
{
    const float* x       = (const float*)d_in[0];
    const float* w1      = (const float*)d_in[1];
    const float* b1      = (const float*)d_in[2];
    const float* w2      = (const float*)d_in[3];
    const float* b2      = (const float*)d_in[4];
    const float* support = (const float*)d_in[5];
    const float* alpha   = (const float*)d_in[6];
    float* out = (float*)d_out;

    static bool attr_set = false;
    if (!attr_set) {
        cudaFuncSetAttribute(gemm_mma, cudaFuncAttributeMaxDynamicSharedMemorySize, GEMM_SMEM);
        attr_set = true;
    }

    pre_kernel<<<CONV_BLOCKS + PREP_BLOCKS, 256>>>(x, w1, b1, w2, b2, support);
    gemm_mma<<<dim3(NIT, NJT), 256, GEMM_SMEM>>>(alpha);
    combine_kernel<<<NIMG * NCLS / 16, 256>>>(out);
}